// round 6
// baseline (speedup 1.0000x reference)
#include <cuda_runtime.h>
#include <cuda_bf16.h>
#include <stdint.h>

#define NN   50000
#define EE   250000
#define FULL 0xffffffffu
#define NBLK 148
#define NTHR 1024

// Static scratch. Invariant: g_cnt == 0 at kernel entry (zero-init at load,
// re-zeroed during the permute phase each launch -> replay-idempotent).
__device__ int   g_cnt[NN];
__device__ int   g_off[NN + 1];
__device__ int   g_cur[NN];
__device__ int2  g_csr[EE];          // (src, ea bits), dst-bucketed
__device__ float g_h[NN * 32];       // node features between layers
__device__ float g_uvr[NN * 96];     // [u | v | r] per node
__device__ int   g_bar_count;
__device__ volatile int g_bar_phase;

// Sense-reversing grid barrier. __threadfence() (gpu scope) both orders the
// writes and emits CCTL.IVALL on sm_103a, invalidating this SM's L1D.
__device__ __forceinline__ void grid_bar(int& myphase) {
    __syncthreads();
    if (threadIdx.x == 0) {
        __threadfence();
        if (atomicAdd(&g_bar_count, 1) == (int)gridDim.x - 1) {
            g_bar_count = 0;
            __threadfence();
            g_bar_phase = myphase + 1;
        } else {
            while (g_bar_phase == myphase) __nanosleep(32);
        }
    }
    __syncthreads();
    myphase++;
}

__global__ void __launch_bounds__(NTHR, 1)
mpnn_persistent(const float* __restrict__ x,
                const int*   __restrict__ ei,
                const float* __restrict__ ea,
                const float* __restrict__ nW,
                const float* __restrict__ nb,
                const float* __restrict__ l1W,
                const float* __restrict__ l1b,
                const float* __restrict__ root,
                const float* __restrict__ convb,
                float* __restrict__ out,
                int N, int E) {
    const int tid     = threadIdx.x;
    const int lane    = tid & 31;
    const int gtid    = blockIdx.x * NTHR + tid;
    const int nthr    = gridDim.x * NTHR;
    const int gwarp   = gtid >> 5;
    const int nwarps  = nthr >> 5;

    int myphase = g_bar_phase;   // stable between launches; same for all threads

    // role split for the GEMM phases: role 0 -> u (W1), 1 -> v (B1), 2 -> r (root)
    const int third  = nwarps / 3;
    const int role   = min(gwarp / third, 2);
    const int rwarp  = gwarp - role * third;
    const int rcount = (role == 2) ? (nwarps - 2 * third) : third;
    const float* Wrole = (role == 0) ? l1W : (role == 1) ? l1b : root;
    float w[32];
#pragma unroll
    for (int i = 0; i < 32; i++) w[i] = __ldg(&Wrole[i * 32 + lane]);
    const float nW_l = __ldg(&nW[lane]);
    const float nb_l = __ldg(&nb[lane]);
    const float cb_l = __ldg(&convb[lane]);

    // ---- P1: degree histogram (g_cnt is 0 at entry) ----
    for (int e = gtid; e < E; e += nthr)
        atomicAdd(&g_cnt[__ldg(&ei[E + e])], 1);
    grid_bar(myphase);

    // ---- P2: exclusive scan (block 0 only) ----
    if (blockIdx.x == 0) {
        __shared__ int wsum[32];
        const int per = (N + NTHR - 1) / NTHR;
        int beg  = tid * per;
        int endi = min(beg + per, N);
        int sum = 0;
        for (int i = beg; i < endi; i++) sum += __ldcg(&g_cnt[i]);
        int v = sum;
#pragma unroll
        for (int o = 1; o < 32; o <<= 1) {
            int t = __shfl_up_sync(FULL, v, o);
            if (lane >= o) v += t;
        }
        int wid = tid >> 5;
        if (lane == 31) wsum[wid] = v;
        __syncthreads();
        if (wid == 0) {
            int wv0 = wsum[lane];
            int wv = wv0;
#pragma unroll
            for (int o = 1; o < 32; o <<= 1) {
                int t = __shfl_up_sync(FULL, wv, o);
                if (lane >= o) wv += t;
            }
            wsum[lane] = wv - wv0;
        }
        __syncthreads();
        int run = v - sum + wsum[wid];
        for (int i = beg; i < endi; i++) {
            g_off[i] = run;
            g_cur[i] = run;
            run += __ldcg(&g_cnt[i]);
        }
        if (tid == NTHR - 1) g_off[N] = run;
    }
    grid_bar(myphase);

    // ---- P3: permute edges into CSR buckets; re-zero g_cnt for next launch ----
    for (int e = gtid; e < E; e += nthr) {
        int dst = __ldg(&ei[E + e]);
        int p = atomicAdd(&g_cur[dst], 1);
        g_csr[p] = make_int2(__ldg(&ei[e]), __float_as_int(__ldg(&ea[e])));
    }
    for (int n = gtid; n < N; n += nthr) g_cnt[n] = 0;
    grid_bar(myphase);

    // ---- 3 layers: gemm (relu + [W1|B1|root]) then gather (mean + combine) ----
    for (int layer = 0; layer < 3; layer++) {
        // GEMM: uvr[n][role*32 + lane] = sum_i relu(h[n][i]) * Wrole[i][lane]
        for (int n = rwarp; n < N; n += rcount) {
            float h = (layer == 0) ? fmaf(__ldg(&x[n]), nW_l, nb_l)
                                   : __ldcg(&g_h[n * 32 + lane]);
            h = fmaxf(h, 0.0f);
            float a0 = 0.f, a1 = 0.f, a2 = 0.f, a3 = 0.f;
#pragma unroll
            for (int i = 0; i < 32; i += 4) {
                a0 = fmaf(__shfl_sync(FULL, h, i + 0), w[i + 0], a0);
                a1 = fmaf(__shfl_sync(FULL, h, i + 1), w[i + 1], a1);
                a2 = fmaf(__shfl_sync(FULL, h, i + 2), w[i + 2], a2);
                a3 = fmaf(__shfl_sync(FULL, h, i + 3), w[i + 3], a3);
            }
            g_uvr[n * 96 + role * 32 + lane] = (a0 + a1) + (a2 + a3);
        }
        grid_bar(myphase);

        // GATHER: h_out[n] = (sum ea*u[src]+v[src]) / max(deg,1) + r[n] + conv_b
        float* dst_buf = (layer == 2) ? out : g_h;
        for (int n = gwarp; n < N; n += nwarps) {
            int start = __ldcg(&g_off[n]);
            int end   = __ldcg(&g_off[n + 1]);
            float acc = 0.f;
            for (int base = start; base < end; base += 32) {
                int m = min(32, end - base);
                int2 sa = make_int2(0, 0);
                if (lane < m) sa = __ldcg(&g_csr[base + lane]);
                for (int j = 0; j < m; j++) {
                    int   ss = __shfl_sync(FULL, sa.x, j);
                    float aa = __int_as_float(__shfl_sync(FULL, sa.y, j));
                    acc = fmaf(aa, __ldcg(&g_uvr[ss * 96 + lane]), acc)
                          + __ldcg(&g_uvr[ss * 96 + 32 + lane]);
                }
            }
            float c = fmaxf((float)(end - start), 1.0f);
            float r = __ldcg(&g_uvr[n * 96 + 64 + lane]);
            dst_buf[n * 32 + lane] = acc / c + r + cb_l;
        }
        if (layer < 2) grid_bar(myphase);
    }
}

extern "C" void kernel_launch(void* const* d_in, const int* in_sizes, int n_in,
                              void* d_out, int out_size) {
    const float* x     = (const float*)d_in[0];
    const int*   ei    = (const int*)d_in[1];
    const float* ea    = (const float*)d_in[2];
    const float* nW    = (const float*)d_in[5];
    const float* nb    = (const float*)d_in[6];
    const float* l1W   = (const float*)d_in[7];
    const float* l1b   = (const float*)d_in[8];
    const float* root  = (const float*)d_in[9];
    const float* convb = (const float*)d_in[10];

    int N = in_sizes[0];      // 50000
    int E = in_sizes[2];      // 250000
    float* out = (float*)d_out;

    mpnn_persistent<<<NBLK, NTHR>>>(x, ei, ea, nW, nb, l1W, l1b, root, convb,
                                    out, N, E);
}

// round 7
// speedup vs baseline: 1.3566x; 1.3566x over previous
#include <cuda_runtime.h>
#include <cuda_bf16.h>
#include <stdint.h>

#define NN 50000
#define EE 250000
#define FULL 0xffffffffu

// Static scratch
__device__ int   g_cnt[NN];
__device__ int   g_off[NN + 1];
__device__ int   g_cur[NN];
__device__ int   g_csr_src[EE];
__device__ float g_csr_ea[EE];
__device__ float g_uvrA[NN * 96];     // [u | v | r] ping
__device__ float g_uvrB[NN * 96];     // [u | v | r] pong

// ---------------- CSR build ----------------
__global__ void hist_kernel(const int* __restrict__ ei, int E) {
    int e = blockIdx.x * blockDim.x + threadIdx.x;
    if (e >= E) return;
    atomicAdd(&g_cnt[ei[E + e]], 1);
}

// single-block exclusive scan over g_cnt -> g_off, g_cur
__global__ void scan_kernel(int N) {
    __shared__ int wsum[32];
    int tid = threadIdx.x, lane = tid & 31, wid = tid >> 5;
    int per = (N + 1023) >> 10;
    int beg = tid * per;
    int endi = min(beg + per, N);
    int sum = 0;
    for (int i = beg; i < endi; i++) sum += g_cnt[i];
    int v = sum;
#pragma unroll
    for (int o = 1; o < 32; o <<= 1) {
        int t = __shfl_up_sync(FULL, v, o);
        if (lane >= o) v += t;
    }
    if (lane == 31) wsum[wid] = v;
    __syncthreads();
    if (wid == 0) {
        int w0 = wsum[lane];
        int wv = w0;
#pragma unroll
        for (int o = 1; o < 32; o <<= 1) {
            int t = __shfl_up_sync(FULL, wv, o);
            if (lane >= o) wv += t;
        }
        wsum[lane] = wv - w0;
    }
    __syncthreads();
    int run = v - sum + wsum[wid];
    for (int i = beg; i < endi; i++) {
        g_off[i] = run;
        g_cur[i] = run;
        run += g_cnt[i];
    }
    if (tid == 1023) g_off[N] = run;
}

__global__ void permute_kernel(const int* __restrict__ ei,
                               const float* __restrict__ ea, int E) {
    int e = blockIdx.x * blockDim.x + threadIdx.x;
    if (e >= E) return;
    int dst = ei[E + e];
    int p = atomicAdd(&g_cur[dst], 1);
    g_csr_src[p] = ei[e];
    g_csr_ea[p] = ea[e];
}

// gemm0: uvrA[n] = relu(x[n]*nW + nb) @ [W1 | B1 | root]
// Weights in registers (loaded once per thread), grid-stride over nodes.
__global__ void __launch_bounds__(256)
gemm0_kernel(const float* __restrict__ x,
             const float* __restrict__ nW,
             const float* __restrict__ nb,
             const float* __restrict__ l1W,
             const float* __restrict__ l1b,
             const float* __restrict__ root, int N) {
    __shared__ float hs[8][33];
    int lane = threadIdx.x & 31, wid = threadIdx.x >> 5;
    float w_u[32], w_v[32], w_r[32];
#pragma unroll
    for (int i = 0; i < 32; i++) {
        w_u[i] = __ldg(&l1W[i * 32 + lane]);
        w_v[i] = __ldg(&l1b[i * 32 + lane]);
        w_r[i] = __ldg(&root[i * 32 + lane]);
    }
    float nWl = __ldg(&nW[lane]);
    float nbl = __ldg(&nb[lane]);
    int warp_g = blockIdx.x * 8 + wid;
    int stride = gridDim.x * 8;
    for (int n = warp_g; n < N; n += stride) {
        float hv = fmaxf(fmaf(__ldg(&x[n]), nWl, nbl), 0.0f);
        hs[wid][lane] = hv;
        __syncwarp();
        float au = 0.f, av = 0.f, ar = 0.f;
#pragma unroll
        for (int i = 0; i < 32; i++) {
            float b = hs[wid][i];
            au = fmaf(b, w_u[i], au);
            av = fmaf(b, w_v[i], av);
            ar = fmaf(b, w_r[i], ar);
        }
        float* o = &g_uvrA[n * 96];
        o[lane]      = au;
        o[32 + lane] = av;
        o[64 + lane] = ar;
        __syncwarp();
    }
}

// ---------------- fused layer (R3-proven) ----------------
__device__ __forceinline__ void load_weights(float* Ws,
                                             const float* __restrict__ l1W,
                                             const float* __restrict__ l1b,
                                             const float* __restrict__ root) {
    for (int k = threadIdx.x; k < 1024; k += blockDim.x) {
        Ws[k]        = l1W[k];
        Ws[1024 + k] = l1b[k];
        Ws[2048 + k] = root[k];
    }
    __syncthreads();
}

__device__ __forceinline__ void shfl_gemm(float rv, const float* Ws, int lane,
                                          float* o) {
    float au = 0.f, av = 0.f, ar = 0.f;
#pragma unroll
    for (int i = 0; i < 32; i++) {
        float b = __shfl_sync(FULL, rv, i);
        au = fmaf(b, Ws[i * 32 + lane], au);
        av = fmaf(b, Ws[1024 + i * 32 + lane], av);
        ar = fmaf(b, Ws[2048 + i * 32 + lane], ar);
    }
    o[lane]      = au;
    o[32 + lane] = av;
    o[64 + lane] = ar;
}

// fused layer: gather mean -> combine -> (relu -> gemm | write out)
__global__ void layer_kernel(const float* __restrict__ uvr_in,
                             float* __restrict__ uvr_out,
                             const float* __restrict__ l1W,
                             const float* __restrict__ l1b,
                             const float* __restrict__ root,
                             const float* __restrict__ convb,
                             float* __restrict__ out,
                             int N, int final_layer) {
    __shared__ float Ws[3 * 1024];
    if (!final_layer) load_weights(Ws, l1W, l1b, root);
    int warp = threadIdx.x >> 5, lane = threadIdx.x & 31;
    int n = blockIdx.x * (blockDim.x >> 5) + warp;
    if (n >= N) return;

    int start = g_off[n], end = g_off[n + 1];
    float acc = 0.f;
    for (int base = start; base < end; base += 32) {
        int m = min(32, end - base);
        int s = 0; float a = 0.f;
        if (lane < m) { s = g_csr_src[base + lane]; a = g_csr_ea[base + lane]; }
        for (int j = 0; j < m; j++) {
            int   ss = __shfl_sync(FULL, s, j);
            float aa = __shfl_sync(FULL, a, j);
            const float* o = &uvr_in[ss * 96];
            acc = fmaf(aa, __ldg(&o[lane]), acc) + __ldg(&o[32 + lane]);
        }
    }
    float c = fmaxf((float)(end - start), 1.0f);
    float h = acc / c + uvr_in[n * 96 + 64 + lane] + convb[lane];

    if (final_layer) { out[n * 32 + lane] = h; return; }
    shfl_gemm(fmaxf(h, 0.f), Ws, lane, &uvr_out[n * 96]);
}

extern "C" void kernel_launch(void* const* d_in, const int* in_sizes, int n_in,
                              void* d_out, int out_size) {
    const float* x     = (const float*)d_in[0];
    const int*   ei    = (const int*)d_in[1];
    const float* ea    = (const float*)d_in[2];
    const float* nW    = (const float*)d_in[5];
    const float* nb    = (const float*)d_in[6];
    const float* l1W   = (const float*)d_in[7];
    const float* l1b   = (const float*)d_in[8];
    const float* root  = (const float*)d_in[9];
    const float* convb = (const float*)d_in[10];

    int N = in_sizes[0];      // 50000
    int E = in_sizes[2];      // 250000
    float* out = (float*)d_out;

    void *p_cnt, *p_A, *p_B;
    cudaGetSymbolAddress(&p_cnt, g_cnt);
    cudaGetSymbolAddress(&p_A, g_uvrA);
    cudaGetSymbolAddress(&p_B, g_uvrB);
    float* A = (float*)p_A;
    float* B = (float*)p_B;

    cudaMemsetAsync(p_cnt, 0, (size_t)N * sizeof(int));

    int tb = 256;
    int blks_e = (E + tb - 1) / tb;
    int blks_w = (N + (tb / 32) - 1) / (tb / 32);   // warp-per-node

    hist_kernel<<<blks_e, tb>>>(ei, E);
    scan_kernel<<<1, 1024>>>(N);
    permute_kernel<<<blks_e, tb>>>(ei, ea, E);

    gemm0_kernel<<<296, tb>>>(x, nW, nb, l1W, l1b, root, N);
    layer_kernel<<<blks_w, tb>>>(A, B, l1W, l1b, root, convb, out, N, 0);
    layer_kernel<<<blks_w, tb>>>(B, A, l1W, l1b, root, convb, out, N, 0);
    layer_kernel<<<blks_w, tb>>>(A, B, l1W, l1b, root, convb, out, N, 1);
}

// round 8
// speedup vs baseline: 1.6426x; 1.2108x over previous
#include <cuda_runtime.h>
#include <cuda_bf16.h>
#include <stdint.h>

#define NN 50000
#define EE 250000
#define FULL 0xffffffffu

// Static scratch
__device__ int   g_cnt[NN];
__device__ int   g_off[NN + 1];
__device__ int   g_cur[NN];
__device__ int   g_part[64];
__device__ int   g_csr_src[EE];
__device__ float g_csr_ea[EE];
__device__ float g_rhA[NN * 32];     // relu(h) ping
__device__ float g_rhB[NN * 32];     // relu(h) pong

// ---------------- CSR build (R3-proven trio) ----------------
__global__ void hist_kernel(const int* __restrict__ ei, int E) {
    int e = blockIdx.x * blockDim.x + threadIdx.x;
    if (e >= E) return;
    atomicAdd(&g_cnt[ei[E + e]], 1);
}

__global__ void scan1_kernel(int N) {
    __shared__ int s[1024];
    int tid = threadIdx.x;
    int i = blockIdx.x * 1024 + tid;
    int v = (i < N) ? g_cnt[i] : 0;
    s[tid] = v;
    __syncthreads();
#pragma unroll
    for (int o = 1; o < 1024; o <<= 1) {
        int t = (tid >= o) ? s[tid - o] : 0;
        __syncthreads();
        s[tid] += t;
        __syncthreads();
    }
    if (i < N) g_off[i + 1] = s[tid];
    if (tid == 1023) g_part[blockIdx.x] = s[1023];
}

__global__ void scan2_kernel(int nb) {
    if (threadIdx.x == 0) {
        int run = 0;
        for (int b = 0; b < nb; b++) { int t = g_part[b]; g_part[b] = run; run += t; }
    }
}

__global__ void scan3_kernel(int N) {
    int i = blockIdx.x * 1024 + threadIdx.x;
    if (i == 0) g_off[0] = 0;
    if (i < N) {
        int v = g_off[i + 1] + g_part[blockIdx.x];
        g_off[i + 1] = v;
        g_cur[i] = v - g_cnt[i];
    }
}

__global__ void permute_kernel(const int* __restrict__ ei,
                               const float* __restrict__ ea, int E) {
    int e = blockIdx.x * blockDim.x + threadIdx.x;
    if (e >= E) return;
    int dst = ei[E + e];
    int p = atomicAdd(&g_cur[dst], 1);
    g_csr_src[p] = ei[e];
    g_csr_ea[p] = ea[e];
}

// ---------------- fused layer ----------------
// s1[n] = sum_e ea_e * rh[src_e],  s0[n] = sum_e rh[src_e]
// h'    = (s1/c) @ W1 + (s0/c) @ B1 + rh[n] @ root + conv_b
// out   = final ? h' : relu(h')
__global__ void layer_kernel(const float* __restrict__ rh_in,
                             float* __restrict__ rh_out,
                             const float* __restrict__ x,
                             const float* __restrict__ nW,
                             const float* __restrict__ nb,
                             const float* __restrict__ l1W,
                             const float* __restrict__ l1b,
                             const float* __restrict__ root,
                             const float* __restrict__ convb,
                             float* __restrict__ out,
                             int N, int first_layer, int final_layer) {
    __shared__ float Ws[3 * 1024];
    for (int k = threadIdx.x; k < 1024; k += blockDim.x) {
        Ws[k]        = l1W[k];
        Ws[1024 + k] = l1b[k];
        Ws[2048 + k] = root[k];
    }
    __syncthreads();

    int warp = threadIdx.x >> 5, lane = threadIdx.x & 31;
    int n = blockIdx.x * (blockDim.x >> 5) + warp;
    if (n >= N) return;

    float nWl = 0.f, nbl = 0.f;
    if (first_layer) { nWl = __ldg(&nW[lane]); nbl = __ldg(&nb[lane]); }

    int start = g_off[n], end = g_off[n + 1];
    float s0 = 0.f, s1 = 0.f;
    for (int base = start; base < end; base += 32) {
        int m = min(32, end - base);
        int s = 0; float a = 0.f;
        if (lane < m) { s = g_csr_src[base + lane]; a = g_csr_ea[base + lane]; }
        if (first_layer) {
            for (int j = 0; j < m; j++) {
                int   ss = __shfl_sync(FULL, s, j);
                float aa = __shfl_sync(FULL, a, j);
                float t = fmaxf(fmaf(__ldg(&x[ss]), nWl, nbl), 0.0f);
                s1 = fmaf(aa, t, s1);
                s0 += t;
            }
        } else {
            for (int j = 0; j < m; j++) {
                int   ss = __shfl_sync(FULL, s, j);
                float aa = __shfl_sync(FULL, a, j);
                float t = __ldg(&rh_in[ss * 32 + lane]);
                s1 = fmaf(aa, t, s1);
                s0 += t;
            }
        }
    }
    float inv = 1.0f / fmaxf((float)(end - start), 1.0f);
    s1 *= inv;
    s0 *= inv;

    float rh = first_layer ? fmaxf(fmaf(__ldg(&x[n]), nWl, nbl), 0.0f)
                           : rh_in[n * 32 + lane];

    float acc = __ldg(&convb[lane]);
#pragma unroll
    for (int i = 0; i < 32; i++) {
        float b1 = __shfl_sync(FULL, s1, i);
        float b0 = __shfl_sync(FULL, s0, i);
        float br = __shfl_sync(FULL, rh, i);
        acc = fmaf(b1, Ws[i * 32 + lane], acc);
        acc = fmaf(b0, Ws[1024 + i * 32 + lane], acc);
        acc = fmaf(br, Ws[2048 + i * 32 + lane], acc);
    }

    if (final_layer) out[n * 32 + lane] = acc;
    else             rh_out[n * 32 + lane] = fmaxf(acc, 0.0f);
}

extern "C" void kernel_launch(void* const* d_in, const int* in_sizes, int n_in,
                              void* d_out, int out_size) {
    const float* x     = (const float*)d_in[0];
    const int*   ei    = (const int*)d_in[1];
    const float* ea    = (const float*)d_in[2];
    const float* nW    = (const float*)d_in[5];
    const float* nb    = (const float*)d_in[6];
    const float* l1W   = (const float*)d_in[7];
    const float* l1b   = (const float*)d_in[8];
    const float* root  = (const float*)d_in[9];
    const float* convb = (const float*)d_in[10];

    int N = in_sizes[0];      // 50000
    int E = in_sizes[2];      // 250000
    float* out = (float*)d_out;

    void *p_cnt, *p_A, *p_B;
    cudaGetSymbolAddress(&p_cnt, g_cnt);
    cudaGetSymbolAddress(&p_A, g_rhA);
    cudaGetSymbolAddress(&p_B, g_rhB);
    float* A = (float*)p_A;
    float* B = (float*)p_B;

    cudaMemsetAsync(p_cnt, 0, (size_t)N * sizeof(int));

    int tb = 256;
    int blks_e = (E + tb - 1) / tb;
    int nb1 = (N + 1023) / 1024;
    int blks_w = (N + (tb / 32) - 1) / (tb / 32);   // warp-per-node

    hist_kernel<<<blks_e, tb>>>(ei, E);
    scan1_kernel<<<nb1, 1024>>>(N);
    scan2_kernel<<<1, 32>>>(nb1);
    scan3_kernel<<<nb1, 1024>>>(N);
    permute_kernel<<<blks_e, tb>>>(ei, ea, E);

    // 3 layers (i = 2 -> 3 layers); layer 0 derives rh from x on the fly
    layer_kernel<<<blks_w, tb>>>(A, A, x, nW, nb, l1W, l1b, root, convb, out, N, 1, 0);
    layer_kernel<<<blks_w, tb>>>(A, B, x, nW, nb, l1W, l1b, root, convb, out, N, 0, 0);
    layer_kernel<<<blks_w, tb>>>(B, A, x, nW, nb, l1W, l1b, root, convb, out, N, 0, 1);
}

// round 9
// speedup vs baseline: 2.3590x; 1.4361x over previous
#include <cuda_runtime.h>
#include <cuda_bf16.h>
#include <stdint.h>

#define NN 50000
#define EE 250000
#define FULL 0xffffffffu

// Static scratch
__device__ int   g_cnt[NN];
__device__ int   g_off[NN + 1];
__device__ int   g_cur[NN];
__device__ int   g_part[64];
__device__ int   g_csr_src[EE];
__device__ float g_csr_ea[EE];
__device__ float g_uvrA[NN * 96];     // [u | v | r] ping
__device__ float g_uvrB[NN * 96];     // [u | v | r] pong

// ---------------- CSR build (R3-proven trio) ----------------
__global__ void hist_kernel(const int* __restrict__ ei, int E) {
    int e = blockIdx.x * blockDim.x + threadIdx.x;
    if (e >= E) return;
    atomicAdd(&g_cnt[ei[E + e]], 1);
}

__global__ void scan1_kernel(int N) {
    __shared__ int s[1024];
    int tid = threadIdx.x;
    int i = blockIdx.x * 1024 + tid;
    int v = (i < N) ? g_cnt[i] : 0;
    s[tid] = v;
    __syncthreads();
#pragma unroll
    for (int o = 1; o < 1024; o <<= 1) {
        int t = (tid >= o) ? s[tid - o] : 0;
        __syncthreads();
        s[tid] += t;
        __syncthreads();
    }
    if (i < N) g_off[i + 1] = s[tid];
    if (tid == 1023) g_part[blockIdx.x] = s[1023];
}

__global__ void scan2_kernel(int nb) {
    if (threadIdx.x == 0) {
        int run = 0;
        for (int b = 0; b < nb; b++) { int t = g_part[b]; g_part[b] = run; run += t; }
    }
}

__global__ void scan3_kernel(int N) {
    int i = blockIdx.x * 1024 + threadIdx.x;
    if (i == 0) g_off[0] = 0;
    if (i < N) {
        int v = g_off[i + 1] + g_part[blockIdx.x];
        g_off[i + 1] = v;
        g_cur[i] = v - g_cnt[i];
    }
}

__global__ void permute_kernel(const int* __restrict__ ei,
                               const float* __restrict__ ea, int E) {
    int e = blockIdx.x * blockDim.x + threadIdx.x;
    if (e >= E) return;
    int dst = ei[E + e];
    int p = atomicAdd(&g_cur[dst], 1);
    g_csr_src[p] = ei[e];
    g_csr_ea[p] = ea[e];
}

// ---------------- shared helpers ----------------
__device__ __forceinline__ void load_weights(float* Ws,
                                             const float* __restrict__ l1W,
                                             const float* __restrict__ l1b,
                                             const float* __restrict__ root) {
    for (int k = threadIdx.x; k < 1024; k += blockDim.x) {
        Ws[k]        = l1W[k];
        Ws[1024 + k] = l1b[k];
        Ws[2048 + k] = root[k];
    }
    __syncthreads();
}

// Node-tiled epilogue: 4 nodes share each weight LDS.
// h[k] lane-distributed; outputs written to uvr rows of n0..n0+3.
__device__ __forceinline__ void tiled_gemm4(const float h[4], const float* Ws,
                                            int lane, int n0, int N,
                                            float* __restrict__ uvr_out) {
    float au[4] = {0.f, 0.f, 0.f, 0.f};
    float av[4] = {0.f, 0.f, 0.f, 0.f};
    float ar[4] = {0.f, 0.f, 0.f, 0.f};
#pragma unroll
    for (int i = 0; i < 32; i++) {
        float wu = Ws[i * 32 + lane];
        float wv = Ws[1024 + i * 32 + lane];
        float wr = Ws[2048 + i * 32 + lane];
#pragma unroll
        for (int k = 0; k < 4; k++) {
            float b = __shfl_sync(FULL, h[k], i);
            au[k] = fmaf(b, wu, au[k]);
            av[k] = fmaf(b, wv, av[k]);
            ar[k] = fmaf(b, wr, ar[k]);
        }
    }
#pragma unroll
    for (int k = 0; k < 4; k++) {
        if (n0 + k < N) {
            float* o = &uvr_out[(n0 + k) * 96];
            o[lane]      = au[k];
            o[32 + lane] = av[k];
            o[64 + lane] = ar[k];
        }
    }
}

// gemm0: uvrA[n] = relu(x[n]*nW + nb) @ [W1 | B1 | root], 4 nodes per warp
__global__ void __launch_bounds__(256)
gemm0_kernel(const float* __restrict__ x,
             const float* __restrict__ nW,
             const float* __restrict__ nb,
             const float* __restrict__ l1W,
             const float* __restrict__ l1b,
             const float* __restrict__ root, int N) {
    __shared__ float Ws[3 * 1024];
    load_weights(Ws, l1W, l1b, root);
    int warp = threadIdx.x >> 5, lane = threadIdx.x & 31;
    int n0 = (blockIdx.x * 8 + warp) * 4;
    if (n0 >= N) return;
    float nWl = __ldg(&nW[lane]);
    float nbl = __ldg(&nb[lane]);
    float h[4];
#pragma unroll
    for (int k = 0; k < 4; k++) {
        int n = n0 + k;
        h[k] = (n < N) ? fmaxf(fmaf(__ldg(&x[n]), nWl, nbl), 0.0f) : 0.0f;
    }
    tiled_gemm4(h, Ws, lane, n0, N, g_uvrA);
}

// fused layer, 4 nodes per warp: gather+combine each (R3 inner loop), then
// shared tiled epilogue (non-final) or direct store (final).
__global__ void __launch_bounds__(256)
layer_kernel(const float* __restrict__ uvr_in,
             float* __restrict__ uvr_out,
             const float* __restrict__ l1W,
             const float* __restrict__ l1b,
             const float* __restrict__ root,
             const float* __restrict__ convb,
             float* __restrict__ out,
             int N, int final_layer) {
    __shared__ float Ws[3 * 1024];
    if (!final_layer) load_weights(Ws, l1W, l1b, root);
    int warp = threadIdx.x >> 5, lane = threadIdx.x & 31;
    int n0 = (blockIdx.x * 8 + warp) * 4;
    if (n0 >= N) return;
    float cbl = __ldg(&convb[lane]);

    float h[4];
#pragma unroll
    for (int k = 0; k < 4; k++) {
        int n = n0 + k;
        if (n >= N) { h[k] = 0.0f; continue; }
        int start = g_off[n], end = g_off[n + 1];
        float acc = 0.f;
        for (int base = start; base < end; base += 32) {
            int m = min(32, end - base);
            int s = 0; float a = 0.f;
            if (lane < m) { s = g_csr_src[base + lane]; a = g_csr_ea[base + lane]; }
            for (int j = 0; j < m; j++) {
                int   ss = __shfl_sync(FULL, s, j);
                float aa = __shfl_sync(FULL, a, j);
                const float* o = &uvr_in[ss * 96];
                acc = fmaf(aa, __ldg(&o[lane]), acc) + __ldg(&o[32 + lane]);
            }
        }
        float c = fmaxf((float)(end - start), 1.0f);
        h[k] = acc / c + uvr_in[n * 96 + 64 + lane] + cbl;
    }

    if (final_layer) {
#pragma unroll
        for (int k = 0; k < 4; k++)
            if (n0 + k < N) out[(n0 + k) * 32 + lane] = h[k];
        return;
    }
#pragma unroll
    for (int k = 0; k < 4; k++) h[k] = fmaxf(h[k], 0.0f);
    tiled_gemm4(h, Ws, lane, n0, N, uvr_out);
}

extern "C" void kernel_launch(void* const* d_in, const int* in_sizes, int n_in,
                              void* d_out, int out_size) {
    const float* x     = (const float*)d_in[0];
    const int*   ei    = (const int*)d_in[1];
    const float* ea    = (const float*)d_in[2];
    const float* nW    = (const float*)d_in[5];
    const float* nb    = (const float*)d_in[6];
    const float* l1W   = (const float*)d_in[7];
    const float* l1b   = (const float*)d_in[8];
    const float* root  = (const float*)d_in[9];
    const float* convb = (const float*)d_in[10];

    int N = in_sizes[0];      // 50000
    int E = in_sizes[2];      // 250000
    float* out = (float*)d_out;

    void *p_cnt, *p_A, *p_B;
    cudaGetSymbolAddress(&p_cnt, g_cnt);
    cudaGetSymbolAddress(&p_A, g_uvrA);
    cudaGetSymbolAddress(&p_B, g_uvrB);
    float* A = (float*)p_A;
    float* B = (float*)p_B;

    cudaMemsetAsync(p_cnt, 0, (size_t)N * sizeof(int));

    int tb = 256;
    int blks_e = (E + tb - 1) / tb;
    int nb1 = (N + 1023) / 1024;
    int blks_t = (N + 31) / 32;    // 4 nodes/warp, 8 warps/block

    hist_kernel<<<blks_e, tb>>>(ei, E);
    scan1_kernel<<<nb1, 1024>>>(N);
    scan2_kernel<<<1, 32>>>(nb1);
    scan3_kernel<<<nb1, 1024>>>(N);
    permute_kernel<<<blks_e, tb>>>(ei, ea, E);

    gemm0_kernel<<<blks_t, tb>>>(x, nW, nb, l1W, l1b, root, N);
    layer_kernel<<<blks_t, tb>>>(A, B, l1W, l1b, root, convb, out, N, 0);
    layer_kernel<<<blks_t, tb>>>(B, A, l1W, l1b, root, convb, out, N, 0);
    layer_kernel<<<blks_t, tb>>>(A, B, l1W, l1b, root, convb, out, N, 1);
}